// round 7
// baseline (speedup 1.0000x reference)
#include <cuda_runtime.h>
#include <cuda_bf16.h>
#include <cstdint>

#define VOCAB  8000
#define HID    256
#define BATCH  32
#define SEQ    256
#define NTOK   (BATCH * SEQ)          // 8192
#define OUT_ROWS NTOK                 // 8192
#define NPAD   8064                   // 63 * 128, zero-padded W_out rows
#define KSPL   512                    // [hi | lo] x 256

// ---------------- device scratch (no allocation allowed) ----------------
__device__ float g_WihT[VOCAB * HID];
__device__ float g_xp  [NTOK * HID];
__device__ float g_Y   [NTOK * HID];
__device__ __align__(128) __nv_bfloat16 g_A2[NTOK * KSPL];   // 8.4 MB
__device__ __align__(128) __nv_bfloat16 g_B2[NPAD * KSPL];   // 8.3 MB

extern __shared__ __align__(1024) char dsmem[];

// ---------------- helpers ----------------------------------------------
__device__ __forceinline__ void ffma2(unsigned long long &d,
                                      unsigned long long a,
                                      unsigned long long b) {
    asm("fma.rn.f32x2 %0, %1, %2, %0;" : "+l"(d) : "l"(a), "l"(b));
}
__device__ __forceinline__ unsigned long long pack2(float lo, float hi) {
    unsigned long long r;
    asm("mov.b64 %0, {%1, %2};" : "=l"(r) : "f"(lo), "f"(hi));
    return r;
}
__device__ __forceinline__ float2 unpack2(unsigned long long v) {
    float2 f;
    asm("mov.b64 {%0, %1}, %2;" : "=f"(f.x), "=f"(f.y) : "l"(v));
    return f;
}
__device__ __forceinline__ uint32_t smem_u32(const void* p) {
    uint32_t a;
    asm("{ .reg .u64 t; cvta.to.shared.u64 t, %1; cvt.u32.u64 %0, t; }"
        : "=r"(a) : "l"(p));
    return a;
}

#define CP_ASYNC16(smem, gmem)                                               \
    asm volatile("cp.async.cg.shared.global [%0], [%1], 16;"                 \
                 :: "r"(smem), "l"(gmem))
#define CP_COMMIT() asm volatile("cp.async.commit_group;" ::: "memory")
#define CP_WAIT0()  asm volatile("cp.async.wait_group 0;" ::: "memory")

#define LDSM_X4(r, addr)                                                     \
    asm volatile("ldmatrix.sync.aligned.m8n8.x4.shared.b16 "                 \
                 "{%0,%1,%2,%3}, [%4];"                                      \
                 : "=r"((r)[0]), "=r"((r)[1]), "=r"((r)[2]), "=r"((r)[3])    \
                 : "r"(addr))

#define MMA16816(d, a, b0, b1)                                               \
    asm volatile("mma.sync.aligned.m16n8k16.row.col.f32.bf16.bf16.f32 "      \
                 "{%0,%1,%2,%3}, {%4,%5,%6,%7}, {%8,%9}, {%0,%1,%2,%3};"     \
                 : "+f"((d)[0]), "+f"((d)[1]), "+f"((d)[2]), "+f"((d)[3])    \
                 : "r"((a)[0]), "r"((a)[1]), "r"((a)[2]), "r"((a)[3]),       \
                   "r"(b0), "r"(b1))

// ---------------- K1: transpose W_ih ------------------------------------
__global__ void transpose_wih(const float* __restrict__ W, float* __restrict__ WT) {
    __shared__ float tile[32][33];
    int v = blockIdx.x * 32 + threadIdx.x;
    int h = blockIdx.y * 32 + threadIdx.y;
    tile[threadIdx.y][threadIdx.x] = W[h * VOCAB + v];
    __syncthreads();
    int v2 = blockIdx.x * 32 + threadIdx.y;
    int h2 = blockIdx.y * 32 + threadIdx.x;
    WT[v2 * HID + h2] = tile[threadIdx.x][threadIdx.y];
}

// ---------------- K2: gather + b_ih -------------------------------------
__global__ void gather_emb(const int* __restrict__ X,
                           const float* __restrict__ bih,
                           const float* __restrict__ WT,
                           float* __restrict__ xp) {
    int tb = blockIdx.x;
    int h  = threadIdx.x;
    int t  = tb >> 5;
    int b  = tb & 31;
    int x  = X[b * SEQ + t];
    xp[tb * HID + h] = WT[x * HID + h] + bih[h];
}

// ---------------- K3: recurrence (unchanged, passing) -------------------
#define KREG 192
#define KSM  64
#define RNN_SMEM ((HID + HID * 65) * (int)sizeof(float))

__global__ __launch_bounds__(256, 1)
void rnn_recurrence(const float* __restrict__ h0,
                    const float* __restrict__ W_hh,
                    const float* __restrict__ b_hh,
                    const float* __restrict__ xp,
                    float* __restrict__ Y,
                    float* __restrict__ h_last) {
    float* smem = (float*)dsmem;
    float* sh_h = smem;
    float* sh_w = smem + HID;

    const int j = threadIdx.x;
    const int b = blockIdx.x;

    unsigned long long wp[96];
    {
        const float2* wrow = (const float2*)(W_hh + j * HID);
        #pragma unroll
        for (int i = 0; i < 96; i++) {
            float2 w = wrow[i];
            wp[i] = pack2(w.x, w.y);
        }
    }
    for (int idx = j; idx < HID * KSM; idx += 256) {
        int jj = idx >> 6, kk = idx & 63;
        sh_w[jj * 65 + kk] = W_hh[jj * HID + KREG + kk];
    }
    sh_h[j] = h0[b * HID + j];
    const float bh = b_hh[j];
    __syncthreads();

    const float* wsr = sh_w + j * 65;

    for (int t = 0; t < SEQ; t++) {
        float xv = xp[(t * BATCH + b) * HID + j];
        unsigned long long acc2 = 0ULL;
        const ulonglong2* hp = (const ulonglong2*)sh_h;
        #pragma unroll
        for (int i = 0; i < 24; i++) {
            ulonglong2 q0 = hp[2 * i];
            ulonglong2 q1 = hp[2 * i + 1];
            ffma2(acc2, q0.x, wp[4 * i + 0]);
            ffma2(acc2, q0.y, wp[4 * i + 1]);
            ffma2(acc2, q1.x, wp[4 * i + 2]);
            ffma2(acc2, q1.y, wp[4 * i + 3]);
        }
        float2 s = unpack2(acc2);
        float acc = s.x + s.y + xv + bh;

        #pragma unroll
        for (int kk = 0; kk < KSM; kk += 4) {
            float4 hq = *(const float4*)(sh_h + KREG + kk);
            acc += hq.x * wsr[kk + 0];
            acc += hq.y * wsr[kk + 1];
            acc += hq.z * wsr[kk + 2];
            acc += hq.w * wsr[kk + 3];
        }
        float hn = tanhf(acc);

        __syncthreads();
        sh_h[j] = hn;
        Y[(t * BATCH + b) * HID + j] = hn;
        if (t == SEQ - 1) h_last[b * HID + j] = hn;
        __syncthreads();
    }
}

// ---------------- K4a/K4b: bf16 hi/lo split, [hi|lo] layout -------------
__global__ void split_A(const float* __restrict__ Y,
                        __nv_bfloat16* __restrict__ A2) {
    int idx = blockIdx.x * 256 + threadIdx.x;
    int m = idx >> 8, k = idx & 255;
    float y = Y[m * HID + k];
    __nv_bfloat16 hi = __float2bfloat16_rn(y);
    __nv_bfloat16 lo = __float2bfloat16_rn(y - __bfloat162float(hi));
    __nv_bfloat16* row = A2 + (size_t)m * KSPL;
    row[k]       = hi;
    row[256 + k] = lo;
}

__global__ void split_B(const float* __restrict__ W,
                        __nv_bfloat16* __restrict__ B2) {
    int idx = blockIdx.x * 256 + threadIdx.x;
    int n = idx >> 8, k = idx & 255;
    float y = (n < VOCAB) ? W[n * HID + k] : 0.f;
    __nv_bfloat16 hi = __float2bfloat16_rn(y);
    __nv_bfloat16 lo = __float2bfloat16_rn(y - __bfloat162float(hi));
    __nv_bfloat16* row = B2 + (size_t)n * KSPL;
    row[k]       = hi;
    row[256 + k] = lo;
}

// ---------------- K5: bf16 HMMA GEMM, smem term-reuse -------------------
// C = Ahi*Bhi^T + Alo*Bhi^T + Ahi*Blo^T + bias ; tile 128x128, chunk K=64
// stage = {Ahi, Alo, Bhi, Blo} blocks, each 128 rows x 72 bf16 (pad)
#define BK       64
#define ASTRIDE  72
#define BLOCK_B  (128 * ASTRIDE * 2)       // 18432 bytes per operand block
#define STAGE_B  (4 * BLOCK_B)             // 73728 per stage
#define GEMM_SMEM (2 * STAGE_B)            // 147456 (double buffer)

__global__ __launch_bounds__(256, 1)
void out_gemm_mma(const __nv_bfloat16* __restrict__ A2,
                  const __nv_bfloat16* __restrict__ B2,
                  const float* __restrict__ bias,
                  float* __restrict__ C) {
    const uint32_t sbase = smem_u32(dsmem);
    const int tid = threadIdx.x, wid = tid >> 5, l = tid & 31;
    const int wm = wid & 3, wn = wid >> 2;          // 4x2 warp grid
    const int m0 = blockIdx.x * 128, n0 = blockIdx.y * 128;

    // gmem/smem fill mapping: per block 1024 16B chunks, 4 per thread
    const int lrow = tid >> 1;                      // 0..127
    const int lc   = (tid & 1) * 4;                 // chunk 0..7, 4 each
    const __nv_bfloat16* gAhi = A2 + (size_t)(m0 + lrow) * KSPL + lc * 8;
    const __nv_bfloat16* gBhi = B2 + (size_t)(n0 + lrow) * KSPL + lc * 8;
    const uint32_t sfill = (lrow * ASTRIDE + lc * 8) * 2;   // within block

    // ldmatrix per-thread offsets (bytes, within operand block)
    const uint32_t offA = ((wm * 32 + (l & 15)) * ASTRIDE + ((l >> 4) & 1) * 8) * 2;
    const uint32_t offB = ((wn * 64 + (l & 7) + ((l >> 4) & 1) * 8) * ASTRIDE +
                           ((l >> 3) & 1) * 8) * 2;

    float acc[2][8][4];
    #pragma unroll
    for (int mb = 0; mb < 2; mb++)
        #pragma unroll
        for (int nb = 0; nb < 8; nb++)
            #pragma unroll
            for (int q = 0; q < 4; q++) acc[mb][nb][q] = 0.f;

    // prologue: stage 0 = K-chunk 0 (hi cols it*64.., lo cols 256+it*64..)
    #pragma unroll
    for (int i = 0; i < 4; i++) {
        CP_ASYNC16(sbase + 0 * BLOCK_B + sfill + i * 16, gAhi + i * 8);
        CP_ASYNC16(sbase + 1 * BLOCK_B + sfill + i * 16, gAhi + 256 + i * 8);
        CP_ASYNC16(sbase + 2 * BLOCK_B + sfill + i * 16, gBhi + i * 8);
        CP_ASYNC16(sbase + 3 * BLOCK_B + sfill + i * 16, gBhi + 256 + i * 8);
    }
    CP_COMMIT();

    for (int it = 0; it < HID / BK; it++) {         // 4 K-chunks
        const int s = it & 1;
        CP_WAIT0();
        __syncthreads();
        if (it + 1 < HID / BK) {
            const uint32_t nb2 = sbase + ((it + 1) & 1) * STAGE_B;
            const __nv_bfloat16* ga = gAhi + (it + 1) * BK;
            const __nv_bfloat16* gb = gBhi + (it + 1) * BK;
            #pragma unroll
            for (int i = 0; i < 4; i++) {
                CP_ASYNC16(nb2 + 0 * BLOCK_B + sfill + i * 16, ga + i * 8);
                CP_ASYNC16(nb2 + 1 * BLOCK_B + sfill + i * 16, ga + 256 + i * 8);
                CP_ASYNC16(nb2 + 2 * BLOCK_B + sfill + i * 16, gb + i * 8);
                CP_ASYNC16(nb2 + 3 * BLOCK_B + sfill + i * 16, gb + 256 + i * 8);
            }
            CP_COMMIT();
        }

        const uint32_t stg = sbase + s * STAGE_B;
        #pragma unroll
        for (int term = 0; term < 3; term++) {
            // term 0: Ahi*Bhi, term 1: Alo*Bhi, term 2: Ahi*Blo
            const uint32_t aS = stg + (term == 1 ? BLOCK_B : 0) + offA;
            const uint32_t bS = stg + 2 * BLOCK_B + (term == 2 ? BLOCK_B : 0) + offB;
            #pragma unroll
            for (int ks = 0; ks < 4; ks++) {
                uint32_t ra0[4], ra1[4], rb[4][4];
                LDSM_X4(ra0, aS + ks * 32);
                LDSM_X4(ra1, aS + ks * 32 + 16 * ASTRIDE * 2);
                #pragma unroll
                for (int p = 0; p < 4; p++)
                    LDSM_X4(rb[p], bS + ks * 32 + p * 16 * ASTRIDE * 2);
                #pragma unroll
                for (int nb = 0; nb < 8; nb++) {
                    uint32_t b0 = rb[nb >> 1][(nb & 1) * 2];
                    uint32_t b1 = rb[nb >> 1][(nb & 1) * 2 + 1];
                    MMA16816(acc[0][nb], ra0, b0, b1);
                    MMA16816(acc[1][nb], ra1, b0, b1);
                }
            }
        }
        __syncthreads();
    }

    // epilogue
    const int g = l >> 2, t4 = l & 3;
    #pragma unroll
    for (int mb = 0; mb < 2; mb++) {
        int row = m0 + wm * 32 + mb * 16 + g;
        float* c0 = C + (size_t)row * VOCAB;
        float* c1 = C + (size_t)(row + 8) * VOCAB;
        #pragma unroll
        for (int nb = 0; nb < 8; nb++) {
            int col = n0 + wn * 64 + nb * 8 + 2 * t4;
            if (col < VOCAB) {
                float2 bv = *(const float2*)(bias + col);
                float2 o0 = { acc[mb][nb][0] + bv.x, acc[mb][nb][1] + bv.y };
                float2 o1 = { acc[mb][nb][2] + bv.x, acc[mb][nb][3] + bv.y };
                *(float2*)(c0 + col) = o0;
                *(float2*)(c1 + col) = o1;
            }
        }
    }
}

// ---------------- launch ------------------------------------------------
extern "C" void kernel_launch(void* const* d_in, const int* in_sizes, int n_in,
                              void* d_out, int out_size) {
    const int*   X     = (const int*)  d_in[0];
    const float* h0    = (const float*)d_in[1];
    const float* W_ih  = (const float*)d_in[2];
    const float* b_ih  = (const float*)d_in[3];
    const float* W_hh  = (const float*)d_in[4];
    const float* b_hh  = (const float*)d_in[5];
    const float* W_out = (const float*)d_in[6];
    const float* b_out = (const float*)d_in[7];
    float* out    = (float*)d_out;
    float* h_last = (float*)d_out + (out_size - BATCH * HID);

    float* WihT; cudaGetSymbolAddress((void**)&WihT, g_WihT);
    float* xp;   cudaGetSymbolAddress((void**)&xp,   g_xp);
    float* Y;    cudaGetSymbolAddress((void**)&Y,    g_Y);
    __nv_bfloat16* A2; cudaGetSymbolAddress((void**)&A2, g_A2);
    __nv_bfloat16* B2; cudaGetSymbolAddress((void**)&B2, g_B2);

    cudaFuncSetAttribute(rnn_recurrence,
                         cudaFuncAttributeMaxDynamicSharedMemorySize, RNN_SMEM);
    cudaFuncSetAttribute(out_gemm_mma,
                         cudaFuncAttributeMaxDynamicSharedMemorySize, GEMM_SMEM);

    transpose_wih<<<dim3(VOCAB / 32, HID / 32), dim3(32, 32)>>>(W_ih, WihT);
    gather_emb<<<NTOK, HID>>>(X, b_ih, WihT, xp);
    split_B<<<(NPAD * HID) / 256, 256>>>(W_out, B2);
    rnn_recurrence<<<BATCH, HID, RNN_SMEM>>>(h0, W_hh, b_hh, xp, Y, h_last);
    split_A<<<(NTOK * HID) / 256, 256>>>(Y, A2);
    out_gemm_mma<<<dim3(OUT_ROWS / 128, NPAD / 128), 256, GEMM_SMEM>>>(
        A2, B2, b_out, out);
}

// round 9
// speedup vs baseline: 1.0120x; 1.0120x over previous
#include <cuda_runtime.h>
#include <cuda_bf16.h>
#include <cstdint>

#define VOCAB  8000
#define HID    256
#define BATCH  32
#define SEQ    256
#define NTOK   (BATCH * SEQ)          // 8192
#define OUT_ROWS NTOK                 // 8192
#define NPAD   8064                   // 63 * 128, zero-padded W_out rows
#define KTOT   768                    // [hi | lo | hi] x 256

// ---------------- device scratch (no allocation allowed) ----------------
__device__ float g_WihT[VOCAB * HID];
__device__ float g_xp  [NTOK * HID];
__device__ float g_Y   [NTOK * HID];
__device__ __align__(128) __nv_bfloat16 g_A2[NTOK * KTOT];   // 12.6 MB
__device__ __align__(128) __nv_bfloat16 g_B2[NPAD * KTOT];   // 12.4 MB

extern __shared__ __align__(1024) char dsmem[];

// ---------------- helpers ----------------------------------------------
__device__ __forceinline__ void ffma2(unsigned long long &d,
                                      unsigned long long a,
                                      unsigned long long b) {
    asm("fma.rn.f32x2 %0, %1, %2, %0;" : "+l"(d) : "l"(a), "l"(b));
}
__device__ __forceinline__ unsigned long long pack2(float lo, float hi) {
    unsigned long long r;
    asm("mov.b64 %0, {%1, %2};" : "=l"(r) : "f"(lo), "f"(hi));
    return r;
}
__device__ __forceinline__ float2 unpack2(unsigned long long v) {
    float2 f;
    asm("mov.b64 {%0, %1}, %2;" : "=f"(f.x), "=f"(f.y) : "l"(v));
    return f;
}
__device__ __forceinline__ uint32_t smem_u32(const void* p) {
    uint32_t a;
    asm("{ .reg .u64 t; cvta.to.shared.u64 t, %1; cvt.u32.u64 %0, t; }"
        : "=r"(a) : "l"(p));
    return a;
}

#define CP_ASYNC16(smem, gmem)                                               \
    asm volatile("cp.async.cg.shared.global [%0], [%1], 16;"                 \
                 :: "r"(smem), "l"(gmem))
#define CP_COMMIT() asm volatile("cp.async.commit_group;" ::: "memory")
#define CP_WAIT0()  asm volatile("cp.async.wait_group 0;" ::: "memory")

#define LDSM_X4(r, addr)                                                     \
    asm volatile("ldmatrix.sync.aligned.m8n8.x4.shared.b16 "                 \
                 "{%0,%1,%2,%3}, [%4];"                                      \
                 : "=r"((r)[0]), "=r"((r)[1]), "=r"((r)[2]), "=r"((r)[3])    \
                 : "r"(addr))

#define MMA16816(d, a, b0, b1)                                               \
    asm volatile("mma.sync.aligned.m16n8k16.row.col.f32.bf16.bf16.f32 "      \
                 "{%0,%1,%2,%3}, {%4,%5,%6,%7}, {%8,%9}, {%0,%1,%2,%3};"     \
                 : "+f"((d)[0]), "+f"((d)[1]), "+f"((d)[2]), "+f"((d)[3])    \
                 : "r"((a)[0]), "r"((a)[1]), "r"((a)[2]), "r"((a)[3]),       \
                   "r"(b0), "r"(b1))

// ---------------- K1: transpose W_ih ------------------------------------
__global__ void transpose_wih(const float* __restrict__ W, float* __restrict__ WT) {
    __shared__ float tile[32][33];
    int v = blockIdx.x * 32 + threadIdx.x;
    int h = blockIdx.y * 32 + threadIdx.y;
    tile[threadIdx.y][threadIdx.x] = W[h * VOCAB + v];
    __syncthreads();
    int v2 = blockIdx.x * 32 + threadIdx.y;
    int h2 = blockIdx.y * 32 + threadIdx.x;
    WT[v2 * HID + h2] = tile[threadIdx.x][threadIdx.y];
}

// ---------------- K2: gather + b_ih -------------------------------------
__global__ void gather_emb(const int* __restrict__ X,
                           const float* __restrict__ bih,
                           const float* __restrict__ WT,
                           float* __restrict__ xp) {
    int tb = blockIdx.x;
    int h  = threadIdx.x;
    int t  = tb >> 5;
    int b  = tb & 31;
    int x  = X[b * SEQ + t];
    xp[tb * HID + h] = WT[x * HID + h] + bih[h];
}

// ---------------- K3: recurrence, v2 ------------------------------------
// 256 thr, thread j owns row j. 208 weights in regs (104 f32x2), 48 in smem
// read as f32x2. Double-buffered h -> ONE barrier/step. 2 accumulators.
#define KREG  208
#define KTAIL 48
#define TSTR  50                       // tail row stride (floats), 8B-aligned
#define RNN_SMEM ((2 * HID + HID * TSTR) * (int)sizeof(float))

__global__ __launch_bounds__(256, 1)
void rnn_recurrence(const float* __restrict__ h0,
                    const float* __restrict__ W_hh,
                    const float* __restrict__ b_hh,
                    const float* __restrict__ xp,
                    float* __restrict__ Y,
                    float* __restrict__ h_last) {
    float* smem = (float*)dsmem;
    float* sh_h = smem;                // [2][256] double buffer
    float* sh_w = smem + 2 * HID;      // [256][TSTR] tail weights

    const int j = threadIdx.x;
    const int b = blockIdx.x;

    // register weights: k in [0,208)
    unsigned long long wp[104];
    {
        const float2* wrow = (const float2*)(W_hh + j * HID);
        #pragma unroll
        for (int i = 0; i < 104; i++) {
            float2 w = wrow[i];
            wp[i] = pack2(w.x, w.y);
        }
    }
    // tail weights: k in [208,256), row-private
    #pragma unroll
    for (int kk = 0; kk < KTAIL; kk++)
        sh_w[j * TSTR + kk] = W_hh[j * HID + KREG + kk];

    sh_h[j] = h0[b * HID + j];
    const float bh = b_hh[j];
    __syncthreads();

    const unsigned long long* wt =
        (const unsigned long long*)(sh_w + j * TSTR);   // 24 x 8B

    for (int t = 0; t < SEQ; t++) {
        const float* hb = sh_h + (t & 1) * HID;
        float*       hw = sh_h + ((t + 1) & 1) * HID;
        float xv = xp[(t * BATCH + b) * HID + j];

        unsigned long long a0 = 0ULL, a1 = 0ULL;
        const ulonglong2* hp = (const ulonglong2*)hb;   // 52 x 16B
        #pragma unroll
        for (int i = 0; i < 26; i++) {                  // 8 k / iter
            ulonglong2 q0 = hp[2 * i];
            ulonglong2 q1 = hp[2 * i + 1];
            ffma2(a0, q0.x, wp[4 * i + 0]);
            ffma2(a1, q0.y, wp[4 * i + 1]);
            ffma2(a0, q1.x, wp[4 * i + 2]);
            ffma2(a1, q1.y, wp[4 * i + 3]);
        }
        // tail: k in [208,256), h + weights both as f32x2
        const unsigned long long* hp2 =
            (const unsigned long long*)(hb + KREG);     // 24 x 8B
        #pragma unroll
        for (int i = 0; i < 24; i += 2) {
            ffma2(a0, hp2[i],     wt[i]);
            ffma2(a1, hp2[i + 1], wt[i + 1]);
        }
        float2 s0 = unpack2(a0), s1 = unpack2(a1);
        float acc = (s0.x + s0.y) + (s1.x + s1.y) + xv + bh;
        float hn = tanhf(acc);

        hw[j] = hn;
        Y[(t * BATCH + b) * HID + j] = hn;
        if (t == SEQ - 1) h_last[b * HID + j] = hn;
        __syncthreads();                 // new h visible; old buffer reusable
    }
}

// ---------------- K4a/K4b: bf16 hi/lo split, K-folded layout ------------
// A2 row: [Ahi(256) | Alo(256) | Ahi(256)] ; B2 row: [Bhi | Bhi | Blo]
__global__ void split_A(const float* __restrict__ Y,
                        __nv_bfloat16* __restrict__ A2) {
    int idx = blockIdx.x * 256 + threadIdx.x;
    int m = idx >> 8, k = idx & 255;
    float y = Y[m * HID + k];
    __nv_bfloat16 hi = __float2bfloat16_rn(y);
    __nv_bfloat16 lo = __float2bfloat16_rn(y - __bfloat162float(hi));
    __nv_bfloat16* row = A2 + (size_t)m * KTOT;
    row[k]       = hi;
    row[256 + k] = lo;
    row[512 + k] = hi;
}

__global__ void split_B(const float* __restrict__ W,
                        __nv_bfloat16* __restrict__ B2) {
    int idx = blockIdx.x * 256 + threadIdx.x;
    int n = idx >> 8, k = idx & 255;
    float y = (n < VOCAB) ? W[n * HID + k] : 0.f;
    __nv_bfloat16 hi = __float2bfloat16_rn(y);
    __nv_bfloat16 lo = __float2bfloat16_rn(y - __bfloat162float(hi));
    __nv_bfloat16* row = B2 + (size_t)n * KTOT;
    row[k]       = hi;
    row[256 + k] = hi;
    row[512 + k] = lo;
}

// ---------------- K5: bf16 HMMA GEMM (round-6 proven version) -----------
#define BK       64
#define ASTRIDE  72
#define STAGE_B  (128 * ASTRIDE * 2)
#define GEMM_SMEM (4 * STAGE_B)

__global__ __launch_bounds__(256, 2)
void out_gemm_mma(const __nv_bfloat16* __restrict__ A2,
                  const __nv_bfloat16* __restrict__ B2,
                  const float* __restrict__ bias,
                  float* __restrict__ C) {
    const uint32_t sbase = smem_u32(dsmem);
    const int tid = threadIdx.x, wid = tid >> 5, l = tid & 31;
    const int wm = wid & 3, wn = wid >> 2;
    const int m0 = blockIdx.x * 128, n0 = blockIdx.y * 128;

    const uint32_t smA = sbase;
    const uint32_t smB = sbase + 2 * STAGE_B;

    const int lrow = tid >> 1;
    const int lc   = (tid & 1) * 4;
    const __nv_bfloat16* gA = A2 + (size_t)(m0 + lrow) * KTOT + lc * 8;
    const __nv_bfloat16* gB = B2 + (size_t)(n0 + lrow) * KTOT + lc * 8;
    const uint32_t sA = smA + (lrow * ASTRIDE + lc * 8) * 2;
    const uint32_t sB = smB + (lrow * ASTRIDE + lc * 8) * 2;

    const uint32_t offA = ((wm * 32 + (l & 15)) * ASTRIDE + ((l >> 4) & 1) * 8) * 2;
    const uint32_t offB = ((wn * 64 + (l & 7) + ((l >> 4) & 1) * 8) * ASTRIDE +
                           ((l >> 3) & 1) * 8) * 2;

    float acc[2][8][4];
    #pragma unroll
    for (int mb = 0; mb < 2; mb++)
        #pragma unroll
        for (int nb = 0; nb < 8; nb++)
            #pragma unroll
            for (int q = 0; q < 4; q++) acc[mb][nb][q] = 0.f;

    #pragma unroll
    for (int i = 0; i < 4; i++) {
        CP_ASYNC16(sA + i * 16, gA + i * 8);
        CP_ASYNC16(sB + i * 16, gB + i * 8);
    }
    CP_COMMIT();

    for (int it = 0; it < KTOT / BK; it++) {
        const int s = it & 1;
        CP_WAIT0();
        __syncthreads();
        if (it + 1 < KTOT / BK) {
            const int s2 = (it + 1) & 1;
            const __nv_bfloat16* ga = gA + (it + 1) * BK;
            const __nv_bfloat16* gb = gB + (it + 1) * BK;
            #pragma unroll
            for (int i = 0; i < 4; i++) {
                CP_ASYNC16(sA + s2 * STAGE_B + i * 16, ga + i * 8);
                CP_ASYNC16(sB + s2 * STAGE_B + i * 16, gb + i * 8);
            }
            CP_COMMIT();
        }

        const uint32_t aS = smA + s * STAGE_B + offA;
        const uint32_t bS = smB + s * STAGE_B + offB;
        #pragma unroll
        for (int ks = 0; ks < 4; ks++) {
            uint32_t ra0[4], ra1[4], rb[4][4];
            LDSM_X4(ra0, aS + ks * 32);
            LDSM_X4(ra1, aS + ks * 32 + 16 * ASTRIDE * 2);
            #pragma unroll
            for (int p = 0; p < 4; p++)
                LDSM_X4(rb[p], bS + ks * 32 + p * 16 * ASTRIDE * 2);
            #pragma unroll
            for (int nb = 0; nb < 8; nb++) {
                uint32_t b0 = rb[nb >> 1][(nb & 1) * 2];
                uint32_t b1 = rb[nb >> 1][(nb & 1) * 2 + 1];
                MMA16816(acc[0][nb], ra0, b0, b1);
                MMA16816(acc[1][nb], ra1, b0, b1);
            }
        }
        __syncthreads();
    }

    const int g = l >> 2, t4 = l & 3;
    #pragma unroll
    for (int mb = 0; mb < 2; mb++) {
        int row = m0 + wm * 32 + mb * 16 + g;
        float* c0 = C + (size_t)row * VOCAB;
        float* c1 = C + (size_t)(row + 8) * VOCAB;
        #pragma unroll
        for (int nb = 0; nb < 8; nb++) {
            int col = n0 + wn * 64 + nb * 8 + 2 * t4;
            if (col < VOCAB) {
                float2 bv = *(const float2*)(bias + col);
                float2 o0 = { acc[mb][nb][0] + bv.x, acc[mb][nb][1] + bv.y };
                float2 o1 = { acc[mb][nb][2] + bv.x, acc[mb][nb][3] + bv.y };
                *(float2*)(c0 + col) = o0;
                *(float2*)(c1 + col) = o1;
            }
        }
    }
}

// ---------------- launch ------------------------------------------------
extern "C" void kernel_launch(void* const* d_in, const int* in_sizes, int n_in,
                              void* d_out, int out_size) {
    const int*   X     = (const int*)  d_in[0];
    const float* h0    = (const float*)d_in[1];
    const float* W_ih  = (const float*)d_in[2];
    const float* b_ih  = (const float*)d_in[3];
    const float* W_hh  = (const float*)d_in[4];
    const float* b_hh  = (const float*)d_in[5];
    const float* W_out = (const float*)d_in[6];
    const float* b_out = (const float*)d_in[7];
    float* out    = (float*)d_out;
    float* h_last = (float*)d_out + (out_size - BATCH * HID);

    float* WihT; cudaGetSymbolAddress((void**)&WihT, g_WihT);
    float* xp;   cudaGetSymbolAddress((void**)&xp,   g_xp);
    float* Y;    cudaGetSymbolAddress((void**)&Y,    g_Y);
    __nv_bfloat16* A2; cudaGetSymbolAddress((void**)&A2, g_A2);
    __nv_bfloat16* B2; cudaGetSymbolAddress((void**)&B2, g_B2);

    cudaFuncSetAttribute(rnn_recurrence,
                         cudaFuncAttributeMaxDynamicSharedMemorySize, RNN_SMEM);
    cudaFuncSetAttribute(out_gemm_mma,
                         cudaFuncAttributeMaxDynamicSharedMemorySize, GEMM_SMEM);

    transpose_wih<<<dim3(VOCAB / 32, HID / 32), dim3(32, 32)>>>(W_ih, WihT);
    gather_emb<<<NTOK, HID>>>(X, b_ih, WihT, xp);
    split_B<<<(NPAD * HID) / 256, 256>>>(W_out, B2);
    rnn_recurrence<<<BATCH, HID, RNN_SMEM>>>(h0, W_hh, b_hh, xp, Y, h_last);
    split_A<<<(NTOK * HID) / 256, 256>>>(Y, A2);
    out_gemm_mma<<<dim3(OUT_ROWS / 128, NPAD / 128), 256, GEMM_SMEM>>>(
        A2, B2, b_out, out);
}